// round 6
// baseline (speedup 1.0000x reference)
#include <cuda_runtime.h>
#include <math.h>

#define BDIM 512
#define TDIM 512
#define IN0  64
#define HDIM 128
#define G3   384   // 3*H  (gate order r, z, n)

typedef unsigned long long u64;

// ---------------------------------------------------------------------------
// f32x2 packed helpers. Lanes now carry adjacent k-values (even k in lo,
// odd k in hi); horizontal add at the end of the reduction.
// ---------------------------------------------------------------------------
__device__ __forceinline__ void fma2(u64& d, u64 a, u64 b) {
    asm("fma.rn.f32x2 %0, %1, %2, %0;" : "+l"(d) : "l"(a), "l"(b));
}
__device__ __forceinline__ float hadd2(u64 v) {
    unsigned int lo, hi;
    asm("mov.b64 {%0, %1}, %2;" : "=r"(lo), "=r"(hi) : "l"(v));
    return __uint_as_float(lo) + __uint_as_float(hi);
}
__device__ __forceinline__ float sigmoid_f(float x) {
    return __fdividef(1.f, 1.f + __expf(-x));
}
__device__ __forceinline__ float tanh_f(float x) {
    // 2*sigmoid(2x) - 1 : MUFU-based, rel err ~1e-6
    return __fmaf_rn(2.f, __fdividef(1.f, 1.f + __expf(-2.f * x)), -1.f);
}

// ---------------------------------------------------------------------------
// Scratch
// ---------------------------------------------------------------------------
__device__ float g_gi   [(size_t)BDIM * TDIM * G3];
__device__ float g_h1   [(size_t)BDIM * TDIM * HDIM];
__device__ float g_hlast[(size_t)BDIM * HDIM];

// ---------------------------------------------------------------------------
// gi GEMM v6: packed-k lanes, natural row-major staging (no transposes,
// no splats). CTA = 64 rows, 256 threads, 4 chunks of 96 gates.
// Thread: 4 rows x 6 gates = 24 packed accumulators.
// Output staged in smem, flushed with coalesced STG.128 (proven v5).
// ---------------------------------------------------------------------------
template <int K>
__global__ __launch_bounds__(256)
void gi_gemm(const float* __restrict__ X,
             const float* __restrict__ W,
             const float* __restrict__ bias)
{
    constexpr int TM = 64;
    constexpr int NC = 96;
    constexpr int XP = K + 2;   // even pitch -> 8B-aligned rows
    constexpr int WP = K + 2;

    extern __shared__ float sm[];
    float* xs = sm;             // [TM][XP] natural
    float* ws = sm + TM * XP;   // [NC][WP] natural; reused as [64][96] staging

    const int tid = threadIdx.x;
    const int rowbase = blockIdx.x * TM;

    for (int idx = tid; idx < TM * K; idx += 256) {
        int r = idx / K, k = idx - r * K;
        xs[r * XP + k] = X[(size_t)(rowbase + r) * K + k];
    }

    const int rg = tid >> 4;    // 0..15 : row group (4 rows)
    const int gg = tid & 15;    // 0..15 : gate group (6 gates)
    float* out = g_gi;

    for (int c = 0; c < 4; ++c) {
        __syncthreads();
        for (int idx = tid; idx < NC * K; idx += 256) {
            int g = idx / K, k = idx - g * K;
            ws[g * WP + k] = W[(size_t)(c * NC + g) * K + k];
        }
        __syncthreads();

        u64 acc[4][6];
        #pragma unroll
        for (int i = 0; i < 4; ++i)
            #pragma unroll
            for (int g = 0; g < 6; ++g) acc[i][g] = 0ull;

        const u64* xp0 = (const u64*)&xs[(rg * 4 + 0) * XP];
        const u64* xp1 = (const u64*)&xs[(rg * 4 + 1) * XP];
        const u64* xp2 = (const u64*)&xs[(rg * 4 + 2) * XP];
        const u64* xp3 = (const u64*)&xs[(rg * 4 + 3) * XP];
        const u64* wp0 = (const u64*)&ws[(gg * 6 + 0) * WP];
        const u64* wp1 = (const u64*)&ws[(gg * 6 + 1) * WP];
        const u64* wp2 = (const u64*)&ws[(gg * 6 + 2) * WP];
        const u64* wp3 = (const u64*)&ws[(gg * 6 + 3) * WP];
        const u64* wp4 = (const u64*)&ws[(gg * 6 + 4) * WP];
        const u64* wp5 = (const u64*)&ws[(gg * 6 + 5) * WP];

        #pragma unroll 8
        for (int k2 = 0; k2 < K / 2; ++k2) {
            u64 x0 = xp0[k2], x1 = xp1[k2], x2 = xp2[k2], x3 = xp3[k2];
            u64 w0 = wp0[k2], w1 = wp1[k2], w2 = wp2[k2];
            u64 w3 = wp3[k2], w4 = wp4[k2], w5 = wp5[k2];
            fma2(acc[0][0], x0, w0); fma2(acc[0][1], x0, w1); fma2(acc[0][2], x0, w2);
            fma2(acc[0][3], x0, w3); fma2(acc[0][4], x0, w4); fma2(acc[0][5], x0, w5);
            fma2(acc[1][0], x1, w0); fma2(acc[1][1], x1, w1); fma2(acc[1][2], x1, w2);
            fma2(acc[1][3], x1, w3); fma2(acc[1][4], x1, w4); fma2(acc[1][5], x1, w5);
            fma2(acc[2][0], x2, w0); fma2(acc[2][1], x2, w1); fma2(acc[2][2], x2, w2);
            fma2(acc[2][3], x2, w3); fma2(acc[2][4], x2, w4); fma2(acc[2][5], x2, w5);
            fma2(acc[3][0], x3, w0); fma2(acc[3][1], x3, w1); fma2(acc[3][2], x3, w2);
            fma2(acc[3][3], x3, w3); fma2(acc[3][4], x3, w4); fma2(acc[3][5], x3, w5);
        }

        __syncthreads();  // done reading weights; reuse ws as staging

        #pragma unroll
        for (int g = 0; g < 6; ++g) {
            float bv = bias[c * NC + gg * 6 + g];
            #pragma unroll
            for (int i = 0; i < 4; ++i)
                ws[(rg * 4 + i) * NC + gg * 6 + g] = hadd2(acc[i][g]) + bv;
        }
        __syncthreads();

        // Coalesced flush: 64 rows x 96 gates, float4 granularity.
        #pragma unroll
        for (int v = 0; v < (TM * NC / 4) / 256; ++v) {
            int idx = (v * 256 + tid) * 4;
            int r = idx / NC, col = idx - r * NC;
            float4 val = *(const float4*)&ws[idx];
            *(float4*)&out[(size_t)(rowbase + r) * G3 + c * NC + col] = val;
        }
    }
}

// ---------------------------------------------------------------------------
// Persistent GRU recurrence v6: packed-k lanes, zero splats.
// 512 thr: j = tid&127 (hidden unit), q = tid>>7 (k-quarter, inter-warp).
// h state stored [b][128] -> broadcast LDS.128 per (b, 4k).
// r/z weight PAIRS in regs (64); n pairs via quad LDS.128 (v5 layout).
// Inner loop per 4k: 24 FFMA2 + 5 LDS.128, nothing else.
// ---------------------------------------------------------------------------
template <int WRITE_SEQ>
__global__ __launch_bounds__(512, 1)
void gru_recurrent(const float* __restrict__ Whh,
                   const float* __restrict__ bhh)
{
    constexpr int RP = 13;

    extern __shared__ float sm[];
    float* Wn4 = sm;                     // [8][512][4] (v5 proven layout)
    float* hs  = Wn4 + 8 * 512 * 4;      // [4][128]  h state, 16B-aligned
    float* red = hs + 4 * HDIM;          // [4][128][RP]

    const int tid = threadIdx.x;
    const int j   = tid & 127;
    const int q   = tid >> 7;
    const int b0  = blockIdx.x * 4;
    const int k0  = q * 32;

    // Stage n-gate weights in consuming-tid quad order (one-time).
    for (int idx = tid; idx < 8 * 512 * 4; idx += 512) {
        int kkg = idx >> 11;
        int rem = idx & 2047;
        int t2  = rem >> 2;
        int m   = rem & 3;
        int j2  = t2 & 127, q2 = t2 >> 7;
        int k2  = q2 * 32 + kkg * 4 + m;
        Wn4[idx] = Whh[(size_t)(2 * HDIM + j2) * HDIM + k2];
    }
    hs[tid] = 0.f;   // 512 = 4*128 exactly

    // r/z weight pairs into registers: wrp[p] = (Wr[j][k0+2p], Wr[j][k0+2p+1]).
    u64 wrp[16], wzp[16];
    {
        const u64* wr64 = (const u64*)(Whh + (size_t)j * HDIM + k0);
        const u64* wz64 = (const u64*)(Whh + (size_t)(HDIM + j) * HDIM + k0);
        #pragma unroll
        for (int p = 0; p < 16; ++p) {
            wrp[p] = __ldg(wr64 + p);
            wzp[p] = __ldg(wz64 + p);
        }
    }
    const float bhr = bhh[j];
    const float bhz = bhh[HDIM + j];
    const float bhn = bhh[2 * HDIM + j];

    __syncthreads();

    float* myred = &red[(q * HDIM + j) * RP];
    const float* gi = g_gi + (size_t)(b0 + q) * TDIM * G3;
    const ulonglong2* wn_l = (const ulonglong2*)Wn4 + tid;   // stride 512/ kkg
    const ulonglong2* hb0 = (const ulonglong2*)(hs + 0 * HDIM + k0);
    const ulonglong2* hb1 = (const ulonglong2*)(hs + 1 * HDIM + k0);
    const ulonglong2* hb2 = (const ulonglong2*)(hs + 2 * HDIM + k0);
    const ulonglong2* hb3 = (const ulonglong2*)(hs + 3 * HDIM + k0);

    for (int t = 0; t < TDIM; ++t) {
        // Prefetch input-side preactivations (covered by the matvec).
        const float* gip = gi + (size_t)t * G3;
        float ir  = gip[j];
        float iz  = gip[HDIM + j];
        float in_ = gip[2 * HDIM + j];

        u64 ar0 = 0, ar1 = 0, ar2 = 0, ar3 = 0;
        u64 az0 = 0, az1 = 0, az2 = 0, az3 = 0;
        u64 an0 = 0, an1 = 0, an2 = 0, an3 = 0;

        #pragma unroll
        for (int kkg = 0; kkg < 8; ++kkg) {
            ulonglong2 wn = wn_l[kkg * 512];   // n pairs (k,k+1),(k+2,k+3)
            ulonglong2 h0 = hb0[kkg];          // broadcast LDS.128
            ulonglong2 h1 = hb1[kkg];
            ulonglong2 h2 = hb2[kkg];
            ulonglong2 h3 = hb3[kkg];
            u64 wr0 = wrp[2 * kkg], wr1 = wrp[2 * kkg + 1];
            u64 wz0 = wzp[2 * kkg], wz1 = wzp[2 * kkg + 1];
            fma2(ar0, wr0, h0.x); fma2(ar0, wr1, h0.y);
            fma2(ar1, wr0, h1.x); fma2(ar1, wr1, h1.y);
            fma2(ar2, wr0, h2.x); fma2(ar2, wr1, h2.y);
            fma2(ar3, wr0, h3.x); fma2(ar3, wr1, h3.y);
            fma2(az0, wz0, h0.x); fma2(az0, wz1, h0.y);
            fma2(az1, wz0, h1.x); fma2(az1, wz1, h1.y);
            fma2(az2, wz0, h2.x); fma2(az2, wz1, h2.y);
            fma2(az3, wz0, h3.x); fma2(az3, wz1, h3.y);
            fma2(an0, wn.x, h0.x); fma2(an0, wn.y, h0.y);
            fma2(an1, wn.x, h1.x); fma2(an1, wn.y, h1.y);
            fma2(an2, wn.x, h2.x); fma2(an2, wn.y, h2.y);
            fma2(an3, wn.x, h3.x); fma2(an3, wn.y, h3.y);
        }

        myred[0]  = hadd2(ar0); myred[1]  = hadd2(ar1);
        myred[2]  = hadd2(ar2); myred[3]  = hadd2(ar3);
        myred[4]  = hadd2(az0); myred[5]  = hadd2(az1);
        myred[6]  = hadd2(az2); myred[7]  = hadd2(az3);
        myred[8]  = hadd2(an0); myred[9]  = hadd2(an1);
        myred[10] = hadd2(an2); myred[11] = hadd2(an3);
        __syncthreads();

        // Gate phase: thread (j, q) finishes batch b = q.
        const int b = q;
        float sr = 0.f, sz = 0.f, sn = 0.f;
        #pragma unroll
        for (int qq = 0; qq < 4; ++qq) {
            const float* rp = &red[(qq * HDIM + j) * RP];
            sr += rp[0 * 4 + b];
            sz += rp[1 * 4 + b];
            sn += rp[2 * 4 + b];
        }
        float r = sigmoid_f(ir + sr + bhr);
        float z = sigmoid_f(iz + sz + bhz);
        float n = tanh_f(in_ + r * (sn + bhn));
        float hold = hs[b * HDIM + j];
        float hnew = n + z * (hold - n);

        hs[b * HDIM + j] = hnew;
        if (WRITE_SEQ) {
            g_h1[((size_t)(b0 + b) * TDIM + t) * HDIM + j] = hnew;  // coalesced
        } else if (t == TDIM - 1) {
            g_hlast[(size_t)(b0 + b) * HDIM + j] = hnew;
        }
        __syncthreads();
    }
}

// ---------------------------------------------------------------------------
// Final FC (O = 1): one warp per batch.
// ---------------------------------------------------------------------------
__global__ void fc_kernel(const float* __restrict__ Wfc,
                          const float* __restrict__ bfc,
                          float* __restrict__ out)
{
    int w = (blockIdx.x * blockDim.x + threadIdx.x) >> 5;
    int lane = threadIdx.x & 31;
    if (w >= BDIM) return;
    const float* hp = g_hlast + (size_t)w * HDIM;
    float s = 0.f;
    #pragma unroll
    for (int k = lane; k < HDIM; k += 32) s += hp[k] * Wfc[k];
    #pragma unroll
    for (int o = 16; o; o >>= 1) s += __shfl_xor_sync(0xFFFFFFFFu, s, o);
    if (lane == 0) out[w] = s + bfc[0];
}

// ---------------------------------------------------------------------------
extern "C" void kernel_launch(void* const* d_in, const int* in_sizes, int n_in,
                              void* d_out, int out_size)
{
    const float* x     = (const float*)d_in[0];
    const float* W_ih0 = (const float*)d_in[1];
    const float* W_hh0 = (const float*)d_in[2];
    const float* b_ih0 = (const float*)d_in[3];
    const float* b_hh0 = (const float*)d_in[4];
    const float* W_ih1 = (const float*)d_in[5];
    const float* W_hh1 = (const float*)d_in[6];
    const float* b_ih1 = (const float*)d_in[7];
    const float* b_hh1 = (const float*)d_in[8];
    const float* W_fc  = (const float*)d_in[9];
    const float* b_fc  = (const float*)d_in[10];
    float* out = (float*)d_out;

    const int SMEM_G64  = (64 * 66  + 96 * 66)  * 4;   // 42,240 B
    const int SMEM_G128 = (64 * 130 + 96 * 130) * 4;   // 83,200 B
    const int SMEM_REC  = (8 * 512 * 4 + 4 * HDIM + 4 * HDIM * 13) * 4; // 94,208 B

    cudaFuncSetAttribute(gi_gemm<64>,  cudaFuncAttributeMaxDynamicSharedMemorySize, SMEM_G64);
    cudaFuncSetAttribute(gi_gemm<128>, cudaFuncAttributeMaxDynamicSharedMemorySize, SMEM_G128);
    cudaFuncSetAttribute(gru_recurrent<1>, cudaFuncAttributeMaxDynamicSharedMemorySize, SMEM_REC);
    cudaFuncSetAttribute(gru_recurrent<0>, cudaFuncAttributeMaxDynamicSharedMemorySize, SMEM_REC);

    void* h1ptr = nullptr;
    cudaGetSymbolAddress(&h1ptr, g_h1);

    const int M = BDIM * TDIM;
    const int GEMM_GRID = M / 64;

    gi_gemm<64><<<GEMM_GRID, 256, SMEM_G64>>>(x, W_ih0, b_ih0);
    gru_recurrent<1><<<BDIM / 4, 512, SMEM_REC>>>(W_hh0, b_hh0);
    gi_gemm<128><<<GEMM_GRID, 256, SMEM_G128>>>((const float*)h1ptr, W_ih1, b_ih1);
    gru_recurrent<0><<<BDIM / 4, 512, SMEM_REC>>>(W_hh1, b_hh1);
    fc_kernel<<<BDIM / 4, 128>>>(W_fc, b_fc, out);
}

// round 7
// speedup vs baseline: 1.1298x; 1.1298x over previous
#include <cuda_runtime.h>
#include <math.h>

#define BDIM 512
#define TDIM 512
#define IN0  64
#define HDIM 128
#define G3   384   // 3*H  (gate order r, z, n)

typedef unsigned long long u64;

// ---------------------------------------------------------------------------
// f32x2 packed helpers (batch-packed lanes, v5 proven scheme)
// ---------------------------------------------------------------------------
__device__ __forceinline__ u64 splat2(unsigned int v) {
    u64 r; asm("mov.b64 %0, {%1, %1};" : "=l"(r) : "r"(v)); return r;
}
__device__ __forceinline__ void fma2(u64& d, u64 a, u64 b) {
    asm("fma.rn.f32x2 %0, %1, %2, %0;" : "+l"(d) : "l"(a), "l"(b));
}
__device__ __forceinline__ float2 unpack2(u64 v) {
    unsigned int lo, hi;
    asm("mov.b64 {%0, %1}, %2;" : "=r"(lo), "=r"(hi) : "l"(v));
    float2 f; f.x = __uint_as_float(lo); f.y = __uint_as_float(hi); return f;
}
__device__ __forceinline__ float sigmoid_f(float x) {
    return __fdividef(1.f, 1.f + __expf(-x));
}
__device__ __forceinline__ float tanh_f(float x) {
    // 2*sigmoid(2x) - 1 : MUFU-based short chain, rel err ~1e-6
    return __fmaf_rn(2.f, __fdividef(1.f, 1.f + __expf(-2.f * x)), -1.f);
}

// ---------------------------------------------------------------------------
// Scratch
// ---------------------------------------------------------------------------
__device__ float g_gi   [(size_t)BDIM * TDIM * G3];
__device__ float g_h1   [(size_t)BDIM * TDIM * HDIM];
__device__ float g_hlast[(size_t)BDIM * HDIM];

// ---------------------------------------------------------------------------
// gi GEMM (v5 proven): out[M,384] = X[M,K] @ W[384,K]^T + bias.
// CTA = 64 rows, 256 thr; output staged in smem, coalesced STG.128 flush.
// ---------------------------------------------------------------------------
template <int K>
__global__ __launch_bounds__(256)
void gi_gemm(const float* __restrict__ X,
             const float* __restrict__ W,
             const float* __restrict__ bias)
{
    constexpr int TM  = 64;
    constexpr int NC  = 96;
    constexpr int XP  = 66;
    constexpr int WP2 = 98;

    extern __shared__ float sm[];
    float* xs = sm;              // [K][XP]
    float* ws = sm + K * XP;     // [K][WP2] weights; reused as [64][96] staging

    const int tid = threadIdx.x;
    const int rowbase = blockIdx.x * TM;

    for (int idx = tid; idx < TM * K; idx += 256) {
        int r = idx / K, k = idx - r * K;
        xs[k * XP + r] = X[(size_t)(rowbase + r) * K + k];
    }

    const int rg = tid >> 4;
    const int gg = tid & 15;
    float* out = g_gi;

    for (int c = 0; c < 4; ++c) {
        __syncthreads();
        for (int idx = tid; idx < NC * K; idx += 256) {
            int g = idx / K, k = idx - g * K;
            ws[k * WP2 + g] = W[(size_t)(c * NC + g) * K + k];
        }
        __syncthreads();

        u64 acc[4][3];
        #pragma unroll
        for (int i = 0; i < 4; ++i)
            #pragma unroll
            for (int p = 0; p < 3; ++p) acc[i][p] = 0ull;

        const float* xp0 = &xs[rg * 4];
        const float* wp0 = &ws[gg * 6];

        #pragma unroll 4
        for (int k = 0; k < K; ++k) {
            u64 x0 = splat2(__float_as_uint(xp0[k * XP + 0]));
            u64 x1 = splat2(__float_as_uint(xp0[k * XP + 1]));
            u64 x2 = splat2(__float_as_uint(xp0[k * XP + 2]));
            u64 x3 = splat2(__float_as_uint(xp0[k * XP + 3]));
            const u64* wrow = (const u64*)&wp0[k * WP2];
            u64 w01 = wrow[0], w23 = wrow[1], w45 = wrow[2];
            fma2(acc[0][0], x0, w01); fma2(acc[0][1], x0, w23); fma2(acc[0][2], x0, w45);
            fma2(acc[1][0], x1, w01); fma2(acc[1][1], x1, w23); fma2(acc[1][2], x1, w45);
            fma2(acc[2][0], x2, w01); fma2(acc[2][1], x2, w23); fma2(acc[2][2], x2, w45);
            fma2(acc[3][0], x3, w01); fma2(acc[3][1], x3, w23); fma2(acc[3][2], x3, w45);
        }

        __syncthreads();  // done reading weights; reuse ws as staging

        const int g0 = c * NC + gg * 6;
        #pragma unroll
        for (int p = 0; p < 3; ++p) {
            float b0 = bias[g0 + 2 * p];
            float b1 = bias[g0 + 2 * p + 1];
            #pragma unroll
            for (int i = 0; i < 4; ++i) {
                float2 v = unpack2(acc[i][p]);
                int r = rg * 4 + i;
                ws[r * NC + gg * 6 + 2 * p]     = v.x + b0;
                ws[r * NC + gg * 6 + 2 * p + 1] = v.y + b1;
            }
        }
        __syncthreads();

        #pragma unroll
        for (int v = 0; v < (TM * NC / 4) / 256; ++v) {
            int idx = (v * 256 + tid) * 4;
            int r = idx / NC, col = idx - r * NC;
            float4 val = *(const float4*)&ws[idx];
            *(float4*)&out[(size_t)(rowbase + r) * G3 + c * NC + col] = val;
        }
    }
}

// ---------------------------------------------------------------------------
// Persistent GRU recurrence v7 = v5 + tail cuts.
// 512 thr: j = tid&127 (hidden unit), q = tid>>7 (k-quarter, inter-warp).
// r/z weights in regs (splats hoisted by ptxas); n weights quad-LDS.128;
// h as one LDS.128 broadcast per k. smem reduction (RP=13), 2 barriers/step.
// Gate phase: own-quarter partials come from registers (3 fewer LDS),
// activations via short MUFU chains.
// ---------------------------------------------------------------------------
template <int WRITE_SEQ>
__global__ __launch_bounds__(512, 1)
void gru_recurrent(const float* __restrict__ Whh,
                   const float* __restrict__ bhh)
{
    constexpr int RP = 13;

    extern __shared__ float sm[];
    float* Wn4 = sm;                     // [8][512][4] quad layout
    float* hs  = Wn4 + 8 * 512 * 4;      // [128][4], 16B-aligned
    float* red = hs + HDIM * 4;          // [4][128][RP]

    const int tid = threadIdx.x;
    const int j   = tid & 127;
    const int q   = tid >> 7;
    const int b0  = blockIdx.x * 4;
    const int k0  = q * 32;

    // Stage n-gate weights in consuming-tid quad order (one-time).
    for (int idx = tid; idx < 8 * 512 * 4; idx += 512) {
        int kkg = idx >> 11;
        int rem = idx & 2047;
        int t2  = rem >> 2;
        int m   = rem & 3;
        int j2  = t2 & 127, q2 = t2 >> 7;
        int k2  = q2 * 32 + kkg * 4 + m;
        Wn4[idx] = Whh[(size_t)(2 * HDIM + j2) * HDIM + k2];
    }
    hs[tid & 511] = 0.f;                 // 512 = 128*4 exactly
    __syncthreads();                      // (also covers red garbage: written before read)

    // r/z weights into registers (k = k0 + kk).
    unsigned int wrz[64];
    #pragma unroll
    for (int kk = 0; kk < 32; ++kk) {
        wrz[2 * kk]     = __float_as_uint(__ldg(Whh + (size_t)j * HDIM + k0 + kk));
        wrz[2 * kk + 1] = __float_as_uint(__ldg(Whh + (size_t)(HDIM + j) * HDIM + k0 + kk));
    }
    const float bhr = bhh[j];
    const float bhz = bhh[HDIM + j];
    const float bhn = bhh[2 * HDIM + j];

    float* myred = &red[(q * HDIM + j) * RP];
    const float* gi = g_gi + (size_t)(b0 + q) * TDIM * G3;
    const ulonglong2* h16 = (const ulonglong2*)hs;     // one 16B broadcast per k
    const uint4* wn4p = (const uint4*)Wn4 + tid;       // stride 512 uint4 per kkg

    for (int t = 0; t < TDIM; ++t) {
        // Prefetch input-side preactivations (covered by the matvec).
        const float* gip = gi + (size_t)t * G3;
        float ir  = gip[j];
        float iz  = gip[HDIM + j];
        float in_ = gip[2 * HDIM + j];

        u64 a_r01 = 0, a_r23 = 0, a_z01 = 0, a_z23 = 0, a_n01 = 0, a_n23 = 0;

        #pragma unroll
        for (int kkg = 0; kkg < 8; ++kkg) {
            uint4 wq = wn4p[kkg * 512];                 // wn for 4 k, coalesced
            #pragma unroll
            for (int m = 0; m < 4; ++m) {
                int kk = kkg * 4 + m;
                ulonglong2 hv = h16[k0 + kk];           // LDS.128 broadcast
                u64 wr2 = splat2(wrz[2 * kk]);          // hoisted by ptxas
                u64 wz2 = splat2(wrz[2 * kk + 1]);
                unsigned int wnu = (m == 0) ? wq.x : (m == 1) ? wq.y
                                 : (m == 2) ? wq.z : wq.w;
                u64 wn2 = splat2(wnu);
                fma2(a_r01, wr2, hv.x); fma2(a_r23, wr2, hv.y);
                fma2(a_z01, wz2, hv.x); fma2(a_z23, wz2, hv.y);
                fma2(a_n01, wn2, hv.x); fma2(a_n23, wn2, hv.y);
            }
        }

        float2 r01 = unpack2(a_r01), r23 = unpack2(a_r23);
        float2 z01 = unpack2(a_z01), z23 = unpack2(a_z23);
        float2 n01 = unpack2(a_n01), n23 = unpack2(a_n23);

        myred[0]  = r01.x; myred[1]  = r01.y;
        myred[2]  = r23.x; myred[3]  = r23.y;
        myred[4]  = z01.x; myred[5]  = z01.y;
        myred[6]  = z23.x; myred[7]  = z23.y;
        myred[8]  = n01.x; myred[9]  = n01.y;
        myred[10] = n23.x; myred[11] = n23.y;

        // Own-quarter partials straight from registers (skip 3 LDS + chain).
        const bool hi  = q >= 2;
        const bool odd = q & 1;
        float ownR = hi ? (odd ? r23.y : r23.x) : (odd ? r01.y : r01.x);
        float ownZ = hi ? (odd ? z23.y : z23.x) : (odd ? z01.y : z01.x);
        float ownN = hi ? (odd ? n23.y : n23.x) : (odd ? n01.y : n01.x);

        __syncthreads();

        // Gate phase: thread (j, q) finishes batch b = q.
        const int b = q;
        float sr = ownR, sz = ownZ, sn = ownN;
        #pragma unroll
        for (int qq = 0; qq < 4; ++qq) {
            if (qq == q) continue;   // q uniform per thread -> predicated out
            const float* rp = &red[(qq * HDIM + j) * RP];
            sr += rp[0 * 4 + b];
            sz += rp[1 * 4 + b];
            sn += rp[2 * 4 + b];
        }
        float r = sigmoid_f(ir + sr + bhr);
        float z = sigmoid_f(iz + sz + bhz);
        float n = tanh_f(in_ + r * (sn + bhn));
        float hold = hs[j * 4 + b];
        float hnew = n + z * (hold - n);

        hs[j * 4 + b] = hnew;
        if (WRITE_SEQ) {
            g_h1[((size_t)(b0 + b) * TDIM + t) * HDIM + j] = hnew;  // coalesced
        } else if (t == TDIM - 1) {
            g_hlast[(size_t)(b0 + b) * HDIM + j] = hnew;
        }
        __syncthreads();
    }
}

// ---------------------------------------------------------------------------
// Final FC (O = 1): one warp per batch.
// ---------------------------------------------------------------------------
__global__ void fc_kernel(const float* __restrict__ Wfc,
                          const float* __restrict__ bfc,
                          float* __restrict__ out)
{
    int w = (blockIdx.x * blockDim.x + threadIdx.x) >> 5;
    int lane = threadIdx.x & 31;
    if (w >= BDIM) return;
    const float* hp = g_hlast + (size_t)w * HDIM;
    float s = 0.f;
    #pragma unroll
    for (int k = lane; k < HDIM; k += 32) s += hp[k] * Wfc[k];
    #pragma unroll
    for (int o = 16; o; o >>= 1) s += __shfl_xor_sync(0xFFFFFFFFu, s, o);
    if (lane == 0) out[w] = s + bfc[0];
}

// ---------------------------------------------------------------------------
extern "C" void kernel_launch(void* const* d_in, const int* in_sizes, int n_in,
                              void* d_out, int out_size)
{
    const float* x     = (const float*)d_in[0];
    const float* W_ih0 = (const float*)d_in[1];
    const float* W_hh0 = (const float*)d_in[2];
    const float* b_ih0 = (const float*)d_in[3];
    const float* b_hh0 = (const float*)d_in[4];
    const float* W_ih1 = (const float*)d_in[5];
    const float* W_hh1 = (const float*)d_in[6];
    const float* b_ih1 = (const float*)d_in[7];
    const float* b_hh1 = (const float*)d_in[8];
    const float* W_fc  = (const float*)d_in[9];
    const float* b_fc  = (const float*)d_in[10];
    float* out = (float*)d_out;

    const int SMEM_G64  = (64  * 66 + 64  * 98) * 4;
    const int SMEM_G128 = (128 * 66 + 128 * 98) * 4;
    const int SMEM_REC  = (8 * 512 * 4 + HDIM * 4 + 4 * HDIM * 13) * 4;  // 92,672 B

    cudaFuncSetAttribute(gi_gemm<64>,  cudaFuncAttributeMaxDynamicSharedMemorySize, SMEM_G64);
    cudaFuncSetAttribute(gi_gemm<128>, cudaFuncAttributeMaxDynamicSharedMemorySize, SMEM_G128);
    cudaFuncSetAttribute(gru_recurrent<1>, cudaFuncAttributeMaxDynamicSharedMemorySize, SMEM_REC);
    cudaFuncSetAttribute(gru_recurrent<0>, cudaFuncAttributeMaxDynamicSharedMemorySize, SMEM_REC);

    void* h1ptr = nullptr;
    cudaGetSymbolAddress(&h1ptr, g_h1);

    const int M = BDIM * TDIM;
    const int GEMM_GRID = M / 64;

    gi_gemm<64><<<GEMM_GRID, 256, SMEM_G64>>>(x, W_ih0, b_ih0);
    gru_recurrent<1><<<BDIM / 4, 512, SMEM_REC>>>(W_hh0, b_hh0);
    gi_gemm<128><<<GEMM_GRID, 256, SMEM_G128>>>((const float*)h1ptr, W_ih1, b_ih1);
    gru_recurrent<0><<<BDIM / 4, 512, SMEM_REC>>>(W_hh1, b_hh1);
    fc_kernel<<<BDIM / 4, 128>>>(W_fc, b_fc, out);
}